// round 15
// baseline (speedup 1.0000x reference)
#include <cuda_runtime.h>
#include <cuda_bf16.h>
#include <cuda_fp16.h>
#include <math.h>
#include <stdint.h>

#define B_   256
#define T_   64
#define BT_  16384
#define DIN_ 2048
#define H_   512
#define H3_  1536
#define H2_  1024
#define NCHUNK 4
#define TCHUNK (T_ / NCHUNK)            // 16 timesteps per chunk
#define MCHUNK (B_ * TCHUNK)            // 4096 t-major rows per chunk

// ---------------- scratch (static device globals; no allocation) ----------------
__device__ __nv_bfloat16 g_in_hi[(size_t)BT_ * DIN_], g_in_lo[(size_t)BT_ * DIN_];
__device__ __half        g_in_f16[(size_t)BT_ * DIN_];
__device__ __half        g_aux_f16[(size_t)BT_ * DIN_];
__device__ __nv_bfloat16 g_wn_hi[(size_t)H_ * DIN_], g_wn_lo[(size_t)H_ * DIN_];  // W_ih i_n rows
__device__ __half        g_wri_f16[(size_t)H2_ * DIN_];   // W_ih i_r|i_i rows
__device__ __half        g_wfh_f16[(size_t)H2_ * DIN_];
__device__ __half        g_wkv_f16[H2_ * H_];
__device__ float         g_bkv[H2_];
__device__ __half        g_gri_f16[(size_t)BT_ * H2_];    // [i_r | i_i] fp16, t-major rows
__device__ __half        g_gf_f16[(size_t)BT_ * H2_];     // [t1 | t2]  fp16, t-major rows
__device__ float         g_in32[(size_t)BT_ * H_];        // i_n fp32, t-major rows
__device__ float         g_kvR[(size_t)BT_ * 2048];       // t-major rows [k0|v0|k1|v1]
__device__ float         g_kvI[(size_t)BT_ * 2048];
__device__ __nv_bfloat16 g_wstep_hi[2048 * H_], g_wstep_lo[2048 * H_];  // [W_hh; Wq]
__device__ float         g_bstep[2048];
__device__ float         g_hx[B_ * H_];
__device__ __nv_bfloat16 g_hx_hi[B_ * H_], g_hx_lo[B_ * H_];
__device__ float         g_stepC[B_ * 2048];

// ---------------- small helpers ----------------
__device__ __forceinline__ void cpasync16(uint32_t s, const void* g) {
    asm volatile("cp.async.cg.shared.global [%0], [%1], 16;\n" :: "r"(s), "l"(g));
}
__device__ __forceinline__ void cp_commit() {
    asm volatile("cp.async.commit_group;\n");
}
template <int N>
__device__ __forceinline__ void cp_wait() {
    asm volatile("cp.async.wait_group %0;\n" :: "n"(N));
}
__device__ __forceinline__ void ldsm4(uint32_t* r, uint32_t addr) {
    asm volatile("ldmatrix.sync.aligned.m8n8.x4.shared.b16 {%0,%1,%2,%3}, [%4];\n"
                 : "=r"(r[0]), "=r"(r[1]), "=r"(r[2]), "=r"(r[3]) : "r"(addr));
}
__device__ __forceinline__ void mma16816(float* c, const uint32_t* a, const uint32_t* b) {
    asm volatile("mma.sync.aligned.m16n8k16.row.col.f32.bf16.bf16.f32 "
                 "{%0,%1,%2,%3}, {%4,%5,%6,%7}, {%8,%9}, {%0,%1,%2,%3};\n"
                 : "+f"(c[0]), "+f"(c[1]), "+f"(c[2]), "+f"(c[3])
                 : "r"(a[0]), "r"(a[1]), "r"(a[2]), "r"(a[3]), "r"(b[0]), "r"(b[1]));
}
__device__ __forceinline__ void mma16816h(float* c, const uint32_t* a, const uint32_t* b) {
    asm volatile("mma.sync.aligned.m16n8k16.row.col.f32.f16.f16.f32 "
                 "{%0,%1,%2,%3}, {%4,%5,%6,%7}, {%8,%9}, {%0,%1,%2,%3};\n"
                 : "+f"(c[0]), "+f"(c[1]), "+f"(c[2]), "+f"(c[3])
                 : "r"(a[0]), "r"(a[1]), "r"(a[2]), "r"(a[3]), "r"(b[0]), "r"(b[1]));
}
// t-major global row G -> bt-major source row
__device__ __forceinline__ int src_row(int G, int tmaj) {
    return tmaj ? ((G & 255) * 64 + (G >> 8)) : G;
}

// ---------------- prep kernels ----------------
__global__ void split_in3(const float* __restrict__ x,
                          __nv_bfloat16* __restrict__ hi,
                          __nv_bfloat16* __restrict__ lo,
                          __half* __restrict__ f16, size_t n)
{
    size_t i = ((size_t)blockIdx.x * blockDim.x + threadIdx.x) * 4;
    if (i >= n) return;
    float4 v = *reinterpret_cast<const float4*>(x + i);
    __nv_bfloat16 h0 = __float2bfloat16(v.x), h1 = __float2bfloat16(v.y);
    __nv_bfloat16 h2 = __float2bfloat16(v.z), h3 = __float2bfloat16(v.w);
    __nv_bfloat162 a, b, c, d;
    a.x = h0; a.y = h1; b.x = h2; b.y = h3;
    c.x = __float2bfloat16(v.x - __bfloat162float(h0));
    c.y = __float2bfloat16(v.y - __bfloat162float(h1));
    d.x = __float2bfloat16(v.z - __bfloat162float(h2));
    d.y = __float2bfloat16(v.w - __bfloat162float(h3));
    *reinterpret_cast<__nv_bfloat162*>(hi + i)     = a;
    *reinterpret_cast<__nv_bfloat162*>(hi + i + 2) = b;
    *reinterpret_cast<__nv_bfloat162*>(lo + i)     = c;
    *reinterpret_cast<__nv_bfloat162*>(lo + i + 2) = d;
    *reinterpret_cast<__half2*>(f16 + i)     = __floats2half2_rn(v.x, v.y);
    *reinterpret_cast<__half2*>(f16 + i + 2) = __floats2half2_rn(v.z, v.w);
}

__global__ void split_bf16(const float* __restrict__ x,
                           __nv_bfloat16* __restrict__ hi,
                           __nv_bfloat16* __restrict__ lo, size_t n)
{
    size_t i = ((size_t)blockIdx.x * blockDim.x + threadIdx.x) * 4;
    if (i >= n) return;
    float4 v = *reinterpret_cast<const float4*>(x + i);
    __nv_bfloat16 h0 = __float2bfloat16(v.x), h1 = __float2bfloat16(v.y);
    __nv_bfloat16 h2 = __float2bfloat16(v.z), h3 = __float2bfloat16(v.w);
    __nv_bfloat162 a, b, c, d;
    a.x = h0; a.y = h1; b.x = h2; b.y = h3;
    c.x = __float2bfloat16(v.x - __bfloat162float(h0));
    c.y = __float2bfloat16(v.y - __bfloat162float(h1));
    d.x = __float2bfloat16(v.z - __bfloat162float(h2));
    d.y = __float2bfloat16(v.w - __bfloat162float(h3));
    *reinterpret_cast<__nv_bfloat162*>(hi + i)     = a;
    *reinterpret_cast<__nv_bfloat162*>(hi + i + 2) = b;
    *reinterpret_cast<__nv_bfloat162*>(lo + i)     = c;
    *reinterpret_cast<__nv_bfloat162*>(lo + i + 2) = d;
}

__global__ void split2_bf16(const float* __restrict__ s1, int n1,
                            const float* __restrict__ s2, int n2,
                            __nv_bfloat16* __restrict__ hi,
                            __nv_bfloat16* __restrict__ lo)
{
    int i = (blockIdx.x * blockDim.x + threadIdx.x) * 4;
    if (i >= n1 + n2) return;
    const float* src = (i < n1) ? s1 + i : s2 + (i - n1);
    float4 v = *reinterpret_cast<const float4*>(src);
    __nv_bfloat16 h0 = __float2bfloat16(v.x), h1 = __float2bfloat16(v.y);
    __nv_bfloat16 h2 = __float2bfloat16(v.z), h3 = __float2bfloat16(v.w);
    __nv_bfloat162 a, b, c, d;
    a.x = h0; a.y = h1; b.x = h2; b.y = h3;
    c.x = __float2bfloat16(v.x - __bfloat162float(h0));
    c.y = __float2bfloat16(v.y - __bfloat162float(h1));
    d.x = __float2bfloat16(v.z - __bfloat162float(h2));
    d.y = __float2bfloat16(v.w - __bfloat162float(h3));
    *reinterpret_cast<__nv_bfloat162*>(hi + i)     = a;
    *reinterpret_cast<__nv_bfloat162*>(hi + i + 2) = b;
    *reinterpret_cast<__nv_bfloat162*>(lo + i)     = c;
    *reinterpret_cast<__nv_bfloat162*>(lo + i + 2) = d;
}

__global__ void conv_f16(const float* __restrict__ x, __half* __restrict__ dst, size_t n)
{
    size_t i = ((size_t)blockIdx.x * blockDim.x + threadIdx.x) * 4;
    if (i >= n) return;
    float4 v = *reinterpret_cast<const float4*>(x + i);
    *reinterpret_cast<__half2*>(dst + i)     = __floats2half2_rn(v.x, v.y);
    *reinterpret_cast<__half2*>(dst + i + 2) = __floats2half2_rn(v.z, v.w);
}

__global__ void conv2_f16(const float* __restrict__ s1, int n1,
                          const float* __restrict__ s2, int n2,
                          __half* __restrict__ dst)
{
    int i = (blockIdx.x * blockDim.x + threadIdx.x) * 4;
    if (i >= n1 + n2) return;
    const float* src = (i < n1) ? s1 + i : s2 + (i - n1);
    float4 v = *reinterpret_cast<const float4*>(src);
    *reinterpret_cast<__half2*>(dst + i)     = __floats2half2_rn(v.x, v.y);
    *reinterpret_cast<__half2*>(dst + i + 2) = __floats2half2_rn(v.z, v.w);
}

__global__ void concat2(float* __restrict__ dst,
                        const float* __restrict__ s1, int n1,
                        const float* __restrict__ s2, int n2)
{
    int i = blockIdx.x * blockDim.x + threadIdx.x;
    if (i < n1 + n2) dst[i] = (i < n1) ? s1[i] : s2[i - n1];
}

// ---------------- split-bf16 3-pass NT GEMM (i_n only) ----------------
// C row index is t-major global row (row_off + tile); A rows gathered via src_row().
__global__ void __launch_bounds__(256)
mma_nt(const __nv_bfloat16* __restrict__ Ahi, const __nv_bfloat16* __restrict__ Alo, int lda,
       const __nv_bfloat16* __restrict__ Bhi, const __nv_bfloat16* __restrict__ Blo, int ldb,
       const float* __restrict__ bias,
       float* __restrict__ Cf, int ldc, int K, int row_off, int tmaj)
{
    extern __shared__ __nv_bfloat16 smem[];
    constexpr int LDK   = 40;
    constexpr int MAT   = 128 * LDK;
    constexpr int STAGE = 4 * MAT;
    const int tid  = threadIdx.x;
    const int lane = tid & 31;
    const int warp = tid >> 5;
    const int wm   = warp >> 2;
    const int wn   = warp & 3;
    const int m0   = blockIdx.y * 128 + row_off;
    const int n0   = blockIdx.x * 128;
    const uint32_t sb = (uint32_t)__cvta_generic_to_shared(smem);

    float c[4][4][4];
#pragma unroll
    for (int i = 0; i < 4; i++)
#pragma unroll
        for (int j = 0; j < 4; j++)
#pragma unroll
            for (int r = 0; r < 4; r++) c[i][j][r] = 0.f;

    const int kc = (tid & 3) * 8;
    auto load_stage = [&](int stage, int k0) {
#pragma unroll
        for (int cchunk = 0; cchunk < 8; cchunk++) {
            int mat = cchunk >> 1;
            int r   = ((cchunk & 1) * 256 + tid) >> 2;
            const __nv_bfloat16* g;
            if (mat == 0)      g = Ahi + (size_t)src_row(m0 + r, tmaj) * lda + k0 + kc;
            else if (mat == 1) g = Alo + (size_t)src_row(m0 + r, tmaj) * lda + k0 + kc;
            else if (mat == 2) g = Bhi + (size_t)(n0 + r) * ldb + k0 + kc;
            else               g = Blo + (size_t)(n0 + r) * ldb + k0 + kc;
            uint32_t s = sb + (uint32_t)(stage * STAGE + mat * MAT + r * LDK + kc) * 2u;
            cpasync16(s, g);
        }
    };

    const int NT = K >> 5;
    load_stage(0, 0);
    cp_commit();

    const int rowA = (lane & 7) + ((lane >> 3) & 1) * 8;
    const int colA = (lane >> 4) * 8;
    const int rowB = (lane & 7) + (lane >> 4) * 8;
    const int colB = ((lane >> 3) & 1) * 8;

    for (int t = 0; t < NT; ++t) {
        if (t + 1 < NT) {
            load_stage((t + 1) & 1, (t + 1) * 32);
            cp_commit();
            cp_wait<1>();
        } else {
            cp_wait<0>();
        }
        __syncthreads();

        const uint32_t st = sb + (uint32_t)((t & 1) * STAGE) * 2u;
#pragma unroll
        for (int kk = 0; kk < 32; kk += 16) {
            uint32_t ah[4][4], al[4][4], bh[2][4], bl[2][4];
#pragma unroll
            for (int im = 0; im < 4; im++) {
                uint32_t off = (uint32_t)((wm * 64 + im * 16 + rowA) * LDK + kk + colA) * 2u;
                ldsm4(ah[im], st + off);
                ldsm4(al[im], st + (uint32_t)(MAT * 2) + off);
            }
#pragma unroll
            for (int p = 0; p < 2; p++) {
                uint32_t off = (uint32_t)((wn * 32 + p * 16 + rowB) * LDK + kk + colB) * 2u;
                ldsm4(bh[p], st + (uint32_t)(2 * MAT * 2) + off);
                ldsm4(bl[p], st + (uint32_t)(3 * MAT * 2) + off);
            }
#pragma unroll
            for (int im = 0; im < 4; im++)
#pragma unroll
                for (int in_ = 0; in_ < 4; in_++) {
                    float* cc = c[im][in_];
                    const uint32_t* bhp = &bh[in_ >> 1][(in_ & 1) * 2];
                    const uint32_t* blp = &bl[in_ >> 1][(in_ & 1) * 2];
                    mma16816(cc, ah[im], bhp);
                    mma16816(cc, ah[im], blp);
                    mma16816(cc, al[im], bhp);
                }
        }
        __syncthreads();
    }

    const int g  = lane >> 2;
    const int tq = lane & 3;
#pragma unroll
    for (int im = 0; im < 4; im++)
#pragma unroll
        for (int in_ = 0; in_ < 4; in_++) {
            int row = m0 + wm * 64 + im * 16 + g;
            int col = n0 + wn * 32 + in_ * 8 + tq * 2;
            float2 bv = *reinterpret_cast<const float2*>(bias + col);
            *reinterpret_cast<float2*>(Cf + (size_t)row * ldc + col) =
                make_float2(c[im][in_][0] + bv.x, c[im][in_][1] + bv.y);
            *reinterpret_cast<float2*>(Cf + (size_t)(row + 8) * ldc + col) =
                make_float2(c[im][in_][2] + bv.x, c[im][in_][3] + bv.y);
        }
}

// ---------------- single-pass fp16 NT GEMM ----------------
template <typename OutT>
__global__ void __launch_bounds__(256)
mma_f16(const __half* __restrict__ A, int lda,
        const __half* __restrict__ B, int ldb,
        const float* __restrict__ bias,
        OutT* __restrict__ C, int ldc, int K, int row_off, int tmaj)
{
    extern __shared__ __half smemh[];
    constexpr int LDK   = 40;
    constexpr int MAT   = 128 * LDK;
    constexpr int STAGE = 2 * MAT;
    const int tid  = threadIdx.x;
    const int lane = tid & 31;
    const int warp = tid >> 5;
    const int wm   = warp >> 2;
    const int wn   = warp & 3;
    const int m0   = blockIdx.y * 128 + row_off;
    const int n0   = blockIdx.x * 128;
    const uint32_t sb = (uint32_t)__cvta_generic_to_shared(smemh);

    float c[4][4][4];
#pragma unroll
    for (int i = 0; i < 4; i++)
#pragma unroll
        for (int j = 0; j < 4; j++)
#pragma unroll
            for (int r = 0; r < 4; r++) c[i][j][r] = 0.f;

    const int kc = (tid & 3) * 8;
    auto load_stage = [&](int stage, int k0) {
#pragma unroll
        for (int cchunk = 0; cchunk < 4; cchunk++) {
            int mat = cchunk >> 1;
            int r   = ((cchunk & 1) * 256 + tid) >> 2;
            const __half* g = (mat == 0)
                ? A + (size_t)src_row(m0 + r, tmaj) * lda + k0 + kc
                : B + (size_t)(n0 + r) * ldb + k0 + kc;
            uint32_t s = sb + (uint32_t)(stage * STAGE + mat * MAT + r * LDK + kc) * 2u;
            cpasync16(s, g);
        }
    };

    const int NT = K >> 5;
    load_stage(0, 0);
    cp_commit();

    const int rowA = (lane & 7) + ((lane >> 3) & 1) * 8;
    const int colA = (lane >> 4) * 8;
    const int rowB = (lane & 7) + (lane >> 4) * 8;
    const int colB = ((lane >> 3) & 1) * 8;

    for (int t = 0; t < NT; ++t) {
        if (t + 1 < NT) {
            load_stage((t + 1) & 1, (t + 1) * 32);
            cp_commit();
            cp_wait<1>();
        } else {
            cp_wait<0>();
        }
        __syncthreads();

        const uint32_t st = sb + (uint32_t)((t & 1) * STAGE) * 2u;
#pragma unroll
        for (int kk = 0; kk < 32; kk += 16) {
            uint32_t ah[4][4], bh[2][4];
#pragma unroll
            for (int im = 0; im < 4; im++) {
                uint32_t off = (uint32_t)((wm * 64 + im * 16 + rowA) * LDK + kk + colA) * 2u;
                ldsm4(ah[im], st + off);
            }
#pragma unroll
            for (int p = 0; p < 2; p++) {
                uint32_t off = (uint32_t)((wn * 32 + p * 16 + rowB) * LDK + kk + colB) * 2u;
                ldsm4(bh[p], st + (uint32_t)(MAT * 2) + off);
            }
#pragma unroll
            for (int im = 0; im < 4; im++)
#pragma unroll
                for (int in_ = 0; in_ < 4; in_++)
                    mma16816h(c[im][in_], ah[im], &bh[in_ >> 1][(in_ & 1) * 2]);
        }
        __syncthreads();
    }

    const int g  = lane >> 2;
    const int tq = lane & 3;
#pragma unroll
    for (int im = 0; im < 4; im++)
#pragma unroll
        for (int in_ = 0; in_ < 4; in_++) {
            int row = m0 + wm * 64 + im * 16 + g;
            int col = n0 + wn * 32 + in_ * 8 + tq * 2;
            float2 bv = *reinterpret_cast<const float2*>(bias + col);
            float v0 = c[im][in_][0] + bv.x, v1 = c[im][in_][1] + bv.y;
            float v2 = c[im][in_][2] + bv.x, v3 = c[im][in_][3] + bv.y;
            if constexpr (sizeof(OutT) == 2) {
                *reinterpret_cast<__half2*>(C + (size_t)row * ldc + col)       = __floats2half2_rn(v0, v1);
                *reinterpret_cast<__half2*>(C + (size_t)(row + 8) * ldc + col) = __floats2half2_rn(v2, v3);
            } else {
                *reinterpret_cast<float2*>(C + (size_t)row * ldc + col)       = make_float2(v0, v1);
                *reinterpret_cast<float2*>(C + (size_t)(row + 8) * ldc + col) = make_float2(v2, v3);
            }
        }
}

// ---------------- step GEMM (sequential phase): 64x64 tile, 4 warps ----------------
__global__ void __launch_bounds__(128)
mma_step(const __nv_bfloat16* __restrict__ Ahi, const __nv_bfloat16* __restrict__ Alo,
         const __nv_bfloat16* __restrict__ Bhi, const __nv_bfloat16* __restrict__ Blo,
         const float* __restrict__ bias,
         float* __restrict__ C)
{
    extern __shared__ __nv_bfloat16 smem_h[];
    constexpr int LDK   = 40;
    constexpr int MAT   = 64 * LDK;
    constexpr int STAGE = 4 * MAT;
    constexpr int LDA   = H_;
    constexpr int LDC   = 2048;
    const int tid  = threadIdx.x;
    const int lane = tid & 31;
    const int warp = tid >> 5;
    const int wm   = warp >> 1;
    const int wn   = warp & 1;
    const int m0   = blockIdx.y * 64;
    const int n0   = blockIdx.x * 64;
    const uint32_t sb = (uint32_t)__cvta_generic_to_shared(smem_h);

    float c[2][4][4];
#pragma unroll
    for (int i = 0; i < 2; i++)
#pragma unroll
        for (int j = 0; j < 4; j++)
#pragma unroll
            for (int r = 0; r < 4; r++) c[i][j][r] = 0.f;

    auto load_stage = [&](int stage, int k0) {
#pragma unroll
        for (int f = tid; f < 256; f += 128) {
            int r  = f >> 2;
            int kc = (f & 3) * 8;
            uint32_t s = sb + (uint32_t)(stage * STAGE + r * LDK + kc) * 2u;
            cpasync16(s,                           Ahi + (size_t)(m0 + r) * LDA + k0 + kc);
            cpasync16(s + (uint32_t)(MAT * 2),     Alo + (size_t)(m0 + r) * LDA + k0 + kc);
            cpasync16(s + (uint32_t)(2 * MAT * 2), Bhi + (size_t)(n0 + r) * LDA + k0 + kc);
            cpasync16(s + (uint32_t)(3 * MAT * 2), Blo + (size_t)(n0 + r) * LDA + k0 + kc);
        }
    };

    constexpr int NT = H_ / 32;
    load_stage(0, 0);
    cp_commit();

    const int rowA = (lane & 7) + ((lane >> 3) & 1) * 8;
    const int colA = (lane >> 4) * 8;
    const int rowB = (lane & 7) + (lane >> 4) * 8;
    const int colB = ((lane >> 3) & 1) * 8;

    for (int t = 0; t < NT; ++t) {
        if (t + 1 < NT) {
            load_stage((t + 1) & 1, (t + 1) * 32);
            cp_commit();
            cp_wait<1>();
        } else {
            cp_wait<0>();
        }
        __syncthreads();

        const uint32_t st = sb + (uint32_t)((t & 1) * STAGE) * 2u;
#pragma unroll
        for (int kk = 0; kk < 32; kk += 16) {
            uint32_t ah[2][4], al[2][4], bh[2][4], bl[2][4];
#pragma unroll
            for (int im = 0; im < 2; im++) {
                uint32_t off = (uint32_t)((wm * 32 + im * 16 + rowA) * LDK + kk + colA) * 2u;
                ldsm4(ah[im], st + off);
                ldsm4(al[im], st + (uint32_t)(MAT * 2) + off);
            }
#pragma unroll
            for (int p = 0; p < 2; p++) {
                uint32_t off = (uint32_t)((wn * 32 + p * 16 + rowB) * LDK + kk + colB) * 2u;
                ldsm4(bh[p], st + (uint32_t)(2 * MAT * 2) + off);
                ldsm4(bl[p], st + (uint32_t)(3 * MAT * 2) + off);
            }
#pragma unroll
            for (int im = 0; im < 2; im++)
#pragma unroll
                for (int in_ = 0; in_ < 4; in_++) {
                    float* cc = c[im][in_];
                    const uint32_t* bhp = &bh[in_ >> 1][(in_ & 1) * 2];
                    const uint32_t* blp = &bl[in_ >> 1][(in_ & 1) * 2];
                    mma16816(cc, ah[im], bhp);
                    mma16816(cc, ah[im], blp);
                    mma16816(cc, al[im], bhp);
                }
        }
        __syncthreads();
    }

    const int g  = lane >> 2;
    const int tq = lane & 3;
#pragma unroll
    for (int im = 0; im < 2; im++)
#pragma unroll
        for (int in_ = 0; in_ < 4; in_++) {
            int row = m0 + wm * 32 + im * 16 + g;
            int col = n0 + wn * 32 + in_ * 8 + tq * 2;
            float2 bv = *reinterpret_cast<const float2*>(bias + col);
            *reinterpret_cast<float2*>(C + (size_t)row * LDC + col) =
                make_float2(c[im][in_][0] + bv.x, c[im][in_][1] + bv.y);
            *reinterpret_cast<float2*>(C + (size_t)(row + 8) * LDC + col) =
                make_float2(c[im][in_][2] + bv.x, c[im][in_][3] + bv.y);
        }
}

// ---------------- per-step attention + GRU gate update (t-major kv/gin) ----------------
__global__ void __launch_bounds__(256)
attn_gate(int t,
          const float* __restrict__ stepC,
          const float* __restrict__ gin,      // i_n fp32 [t*256+b, 512]
          const float* __restrict__ kvR,
          const float* __restrict__ kvI,
          float* __restrict__ hx,
          __nv_bfloat16* __restrict__ hxh,
          __nv_bfloat16* __restrict__ hxl,
          float* __restrict__ out)
{
    const int b   = blockIdx.x;
    const int tid = threadIdx.x;
    const int tm  = t * B_ + b;              // t-major row
    const int bt  = b * T_ + t;              // bt-major row (output)
    const int h   = tid * 2;
    const float* rowC = stepC + (size_t)b * 2048;
    const float* kR   = kvR + (size_t)tm * 2048;
    const float* kI   = kvI + (size_t)tm * 2048;

    float2 qv  = *reinterpret_cast<const float2*>(rowC + 1536 + h);
    float2 kr0 = *reinterpret_cast<const float2*>(kR + h);
    float2 kr1 = *reinterpret_cast<const float2*>(kR + 1024 + h);
    float2 ki0 = *reinterpret_cast<const float2*>(kI + h);
    float2 ki1 = *reinterpret_cast<const float2*>(kI + 1024 + h);

    float s0r = qv.x * kr0.x + qv.y * kr0.y;
    float s1r = qv.x * kr1.x + qv.y * kr1.y;
    float s0i = qv.x * ki0.x + qv.y * ki0.y;
    float s1i = qv.x * ki1.x + qv.y * ki1.y;

#pragma unroll
    for (int o = 16; o > 0; o >>= 1) {
        s0r += __shfl_down_sync(0xffffffffu, s0r, o);
        s1r += __shfl_down_sync(0xffffffffu, s1r, o);
        s0i += __shfl_down_sync(0xffffffffu, s0i, o);
        s1i += __shfl_down_sync(0xffffffffu, s1i, o);
    }
    __shared__ float red[4][8];
    __shared__ float p[4];
    int warp = tid >> 5, lane = tid & 31;
    if (lane == 0) { red[0][warp] = s0r; red[1][warp] = s1r; red[2][warp] = s0i; red[3][warp] = s1i; }
    __syncthreads();
    if (tid == 0) {
        float t0 = 0.f, t1 = 0.f, t2 = 0.f, t3 = 0.f;
#pragma unroll
        for (int w = 0; w < 8; w++) { t0 += red[0][w]; t1 += red[1][w]; t2 += red[2][w]; t3 += red[3][w]; }
        const float scale = 0.044194173824159216f;  // 1/sqrt(512)
        t0 *= scale; t1 *= scale; t2 *= scale; t3 *= scale;
        float mr = fmaxf(t0, t1);
        float e0 = expf(t0 - mr), e1 = expf(t1 - mr);
        float inv = 1.f / (e0 + e1);
        p[0] = e0 * inv; p[1] = e1 * inv;
        float mi = fmaxf(t2, t3);
        float f0 = expf(t2 - mi), f1 = expf(t3 - mi);
        float inv2 = 1.f / (f0 + f1);
        p[2] = f0 * inv2; p[3] = f1 * inv2;
    }
    __syncthreads();
    float p0r = p[0], p1r = p[1], p0i = p[2], p1i = p[3];

    float2 vr0 = *reinterpret_cast<const float2*>(kR + 512 + h);
    float2 vr1 = *reinterpret_cast<const float2*>(kR + 1536 + h);
    float2 vi0 = *reinterpret_cast<const float2*>(kI + 512 + h);
    float2 vi1 = *reinterpret_cast<const float2*>(kI + 1536 + h);
    float2 h_r = *reinterpret_cast<const float2*>(rowC + h);
    float2 h_i = *reinterpret_cast<const float2*>(rowC + 512 + h);
    float2 h_n = *reinterpret_cast<const float2*>(rowC + 1024 + h);
    float2 i_n = *reinterpret_cast<const float2*>(gin + (size_t)tm * H_ + h);
    float2 hv  = *reinterpret_cast<const float2*>(hx + (size_t)b * H_ + h);

    float rg0 = 1.f / (1.f + expf(-(p0r * vr0.x + p1r * vr1.x + h_r.x)));
    float rg1 = 1.f / (1.f + expf(-(p0r * vr0.y + p1r * vr1.y + h_r.y)));
    float ig0 = 1.f / (1.f + expf(-(p0i * vi0.x + p1i * vi1.x + h_i.x)));
    float ig1 = 1.f / (1.f + expf(-(p0i * vi0.y + p1i * vi1.y + h_i.y)));
    float ng0 = tanhf(fmaf(rg0, h_n.x, i_n.x));
    float ng1 = tanhf(fmaf(rg1, h_n.y, i_n.y));
    float hy0 = ng0 + ig0 * (hv.x - ng0);
    float hy1 = ng1 + ig1 * (hv.y - ng1);

    *reinterpret_cast<float2*>(out + (size_t)bt * H_ + h) = make_float2(hy0, hy1);
    *reinterpret_cast<float2*>(hx + (size_t)b * H_ + h)   = make_float2(hy0, hy1);

    __nv_bfloat162 hh, ll;
    hh.x = __float2bfloat16(hy0);
    hh.y = __float2bfloat16(hy1);
    ll.x = __float2bfloat16(hy0 - __bfloat162float(hh.x));
    ll.y = __float2bfloat16(hy1 - __bfloat162float(hh.y));
    *reinterpret_cast<__nv_bfloat162*>(hxh + (size_t)b * H_ + h) = hh;
    *reinterpret_cast<__nv_bfloat162*>(hxl + (size_t)b * H_ + h) = ll;
}

// ---------------- launcher ----------------
extern "C" void kernel_launch(void* const* d_in, const int* in_sizes, int n_in,
                              void* d_out, int out_size)
{
    const float* input = (const float*)d_in[0];
    const float* aux0  = (const float*)d_in[1];
    const float* W_ih  = (const float*)d_in[2];
    const float* b_ih  = (const float*)d_in[3];
    const float* W_fh0 = (const float*)d_in[4];
    const float* b_fh0 = (const float*)d_in[5];
    const float* W_hh  = (const float*)d_in[6];
    const float* b_hh  = (const float*)d_in[7];
    const float* Wq    = (const float*)d_in[8];
    const float* bq    = (const float*)d_in[9];
    const float* Wk    = (const float*)d_in[10];
    const float* bk    = (const float*)d_in[11];
    const float* Wv    = (const float*)d_in[12];
    const float* bv    = (const float*)d_in[13];
    float* out = (float*)d_out;

    __nv_bfloat16 *in_hi, *in_lo, *wn_hi, *wn_lo, *wstep_hi, *wstep_lo, *hx_hi, *hx_lo;
    __half *in_f16, *aux_f16, *wri_f16, *wfh_f16, *wkv_f16, *gri_f16, *gf_f16;
    float *bkv, *gin32, *kvR, *kvI, *bstep, *hx, *stepC;
    cudaGetSymbolAddress((void**)&in_hi,    g_in_hi);
    cudaGetSymbolAddress((void**)&in_lo,    g_in_lo);
    cudaGetSymbolAddress((void**)&in_f16,   g_in_f16);
    cudaGetSymbolAddress((void**)&aux_f16,  g_aux_f16);
    cudaGetSymbolAddress((void**)&wn_hi,    g_wn_hi);
    cudaGetSymbolAddress((void**)&wn_lo,    g_wn_lo);
    cudaGetSymbolAddress((void**)&wri_f16,  g_wri_f16);
    cudaGetSymbolAddress((void**)&wfh_f16,  g_wfh_f16);
    cudaGetSymbolAddress((void**)&wkv_f16,  g_wkv_f16);
    cudaGetSymbolAddress((void**)&gri_f16,  g_gri_f16);
    cudaGetSymbolAddress((void**)&gf_f16,   g_gf_f16);
    cudaGetSymbolAddress((void**)&gin32,    g_in32);
    cudaGetSymbolAddress((void**)&bkv,      g_bkv);
    cudaGetSymbolAddress((void**)&kvR,      g_kvR);
    cudaGetSymbolAddress((void**)&kvI,      g_kvI);
    cudaGetSymbolAddress((void**)&wstep_hi, g_wstep_hi);
    cudaGetSymbolAddress((void**)&wstep_lo, g_wstep_lo);
    cudaGetSymbolAddress((void**)&bstep,    g_bstep);
    cudaGetSymbolAddress((void**)&hx,       g_hx);
    cudaGetSymbolAddress((void**)&hx_hi,    g_hx_hi);
    cudaGetSymbolAddress((void**)&hx_lo,    g_hx_lo);
    cudaGetSymbolAddress((void**)&stepC,    g_stepC);

    constexpr int SMEM_BF   = 81920;
    cudaFuncSetAttribute(mma_nt, cudaFuncAttributeMaxDynamicSharedMemorySize, SMEM_BF);
    constexpr int SMEM_F16  = 40960;
    constexpr int SMEM_STEP = 4 * 64 * 40 * 2 * 2;

    // fork stream + events (created per call; leaked deliberately — stream/event
    // destruction during capture is illegal, and kernel_launch runs only twice)
    cudaStream_t s2;
    cudaStreamCreateWithFlags(&s2, cudaStreamNonBlocking);
    cudaEvent_t evc[NCHUNK], evdone;
    for (int c = 0; c < NCHUNK; c++) cudaEventCreateWithFlags(&evc[c], cudaEventDisableTiming);
    cudaEventCreateWithFlags(&evdone, cudaEventDisableTiming);

    auto nblk = [](size_t n) { return (unsigned)((n / 4 + 255) / 256); };

    // ---- prep (origin stream) ----
    split_in3<<<nblk((size_t)BT_ * DIN_), 256>>>(input, in_hi, in_lo, in_f16, (size_t)BT_ * DIN_);
    conv_f16<<<nblk((size_t)BT_ * DIN_), 256>>>(aux0, aux_f16, (size_t)BT_ * DIN_);
    conv_f16<<<nblk((size_t)H2_ * DIN_), 256>>>(W_ih, wri_f16, (size_t)H2_ * DIN_);
    split_bf16<<<nblk((size_t)H_ * DIN_), 256>>>(W_ih + (size_t)H2_ * DIN_, wn_hi, wn_lo,
                                                 (size_t)H_ * DIN_);
    conv_f16<<<nblk((size_t)H2_ * DIN_), 256>>>(W_fh0, wfh_f16, (size_t)H2_ * DIN_);
    conv2_f16<<<(H2_ * H_ / 4 + 255) / 256, 256>>>(Wk, H_ * H_, Wv, H_ * H_, wkv_f16);
    split2_bf16<<<(2048 * H_ / 4 + 255) / 256, 256>>>(W_hh, H3_ * H_, Wq, H_ * H_, wstep_hi, wstep_lo);
    concat2<<<(H2_ + 255) / 256, 256>>>(bkv, bk, H_, bv, H_);
    concat2<<<(2048 + 255) / 256, 256>>>(bstep, b_hh, H3_, bq, H_);
    cudaMemsetAsync(hx, 0, (size_t)B_ * H_ * sizeof(float));
    cudaMemsetAsync(hx_hi, 0, (size_t)B_ * H_ * sizeof(__nv_bfloat16));
    cudaMemsetAsync(hx_lo, 0, (size_t)B_ * H_ * sizeof(__nv_bfloat16));

    // ---- parallel phase: chunked over t-major rows (origin stream) ----
    const dim3 grid_ri(H2_ / 128, MCHUNK / 128);
    const dim3 grid_in(H_ / 128, MCHUNK / 128);
    for (int c = 0; c < NCHUNK; c++) {
        const int ro = c * MCHUNK;
        // [i_r|i_i] fp16 (A rows gathered bt-major -> t-major out)
        mma_f16<__half><<<grid_ri, 256, SMEM_F16>>>(
            in_f16, DIN_, wri_f16, DIN_, b_ih, gri_f16, H2_, DIN_, ro, 1);
        // [t1|t2] fp16
        mma_f16<__half><<<grid_ri, 256, SMEM_F16>>>(
            aux_f16, DIN_, wfh_f16, DIN_, b_fh0, gf_f16, H2_, DIN_, ro, 1);
        // i_n 3-pass bf16 -> fp32
        mma_nt<<<grid_in, 256, SMEM_BF>>>(
            in_hi, in_lo, DIN_, wn_hi, wn_lo, DIN_, b_ih + H2_, gin32, H_, DIN_, ro, 1);
        // KV projections (A already t-major)
        mma_f16<float><<<grid_ri, 256, SMEM_F16>>>(
            gf_f16, H2_, wkv_f16, H_, bkv, kvR, 2048, H_, ro, 0);
        mma_f16<float><<<grid_ri, 256, SMEM_F16>>>(
            gri_f16, H2_, wkv_f16, H_, bkv, kvR + 1024, 2048, H_, ro, 0);
        mma_f16<float><<<grid_ri, 256, SMEM_F16>>>(
            gf_f16 + 512, H2_, wkv_f16, H_, bkv, kvI, 2048, H_, ro, 0);
        mma_f16<float><<<grid_ri, 256, SMEM_F16>>>(
            gri_f16 + 512, H2_, wkv_f16, H_, bkv, kvI + 1024, 2048, H_, ro, 0);
        cudaEventRecord(evc[c], 0);
    }

    // ---- sequential phase on forked stream, gated per chunk ----
    for (int c = 0; c < NCHUNK; c++) {
        cudaStreamWaitEvent(s2, evc[c], 0);
        for (int t = c * TCHUNK; t < (c + 1) * TCHUNK; ++t) {
            mma_step<<<dim3(2048 / 64, B_ / 64), 128, SMEM_STEP, s2>>>(
                hx_hi, hx_lo, wstep_hi, wstep_lo, bstep, stepC);
            attn_gate<<<B_, 256, 0, s2>>>(t, stepC, gin32, kvR, kvI, hx, hx_hi, hx_lo, out);
        }
    }
    cudaEventRecord(evdone, s2);
    cudaStreamWaitEvent(0, evdone, 0);

    // h_last (origin stream, after join)
    if (out_size >= (int)((size_t)BT_ * H_ + (size_t)B_ * H_)) {
        cudaMemcpyAsync(out + (size_t)BT_ * H_, hx,
                        (size_t)B_ * H_ * sizeof(float), cudaMemcpyDeviceToDevice);
    }
}

// round 16
// speedup vs baseline: 1.0311x; 1.0311x over previous
#include <cuda_runtime.h>
#include <cuda_bf16.h>
#include <cuda_fp16.h>
#include <math.h>
#include <stdint.h>

#define B_   256
#define T_   64
#define BT_  16384
#define DIN_ 2048
#define H_   512
#define H3_  1536
#define H2_  1024
#define NCHUNK 8
#define TCHUNK (T_ / NCHUNK)            // 8 timesteps per chunk
#define MCHUNK (B_ * TCHUNK)            // 2048 t-major rows per chunk

// ---------------- scratch (static device globals; no allocation) ----------------
__device__ __half        g_in_f16[(size_t)BT_ * DIN_];
__device__ __half        g_aux_f16[(size_t)BT_ * DIN_];
__device__ __half        g_wih_f16[(size_t)H3_ * DIN_];
__device__ __half        g_wfh_f16[(size_t)H2_ * DIN_];
__device__ __half        g_wkv_f16[H2_ * H_];
__device__ float         g_bkv[H2_];
__device__ __half        g_gi_f16[(size_t)BT_ * H3_];     // [i_r|i_i|i_n] fp16, t-major rows
__device__ __half        g_gf_f16[(size_t)BT_ * H2_];     // [t1|t2] fp16, t-major rows
__device__ float         g_in32[(size_t)BT_ * H_];        // i_n fp32, t-major rows
__device__ float         g_kvR[(size_t)BT_ * 2048];       // t-major rows [k0|v0|k1|v1]
__device__ float         g_kvI[(size_t)BT_ * 2048];
__device__ __nv_bfloat16 g_wstep_hi[2048 * H_], g_wstep_lo[2048 * H_];  // [W_hh; Wq]
__device__ float         g_bstep[2048];
__device__ float         g_hx[B_ * H_];
__device__ __nv_bfloat16 g_hx_hi[B_ * H_], g_hx_lo[B_ * H_];
__device__ float         g_stepC[B_ * 2048];

// ---------------- small helpers ----------------
__device__ __forceinline__ void cpasync16(uint32_t s, const void* g) {
    asm volatile("cp.async.cg.shared.global [%0], [%1], 16;\n" :: "r"(s), "l"(g));
}
__device__ __forceinline__ void cp_commit() {
    asm volatile("cp.async.commit_group;\n");
}
template <int N>
__device__ __forceinline__ void cp_wait() {
    asm volatile("cp.async.wait_group %0;\n" :: "n"(N));
}
__device__ __forceinline__ void ldsm4(uint32_t* r, uint32_t addr) {
    asm volatile("ldmatrix.sync.aligned.m8n8.x4.shared.b16 {%0,%1,%2,%3}, [%4];\n"
                 : "=r"(r[0]), "=r"(r[1]), "=r"(r[2]), "=r"(r[3]) : "r"(addr));
}
__device__ __forceinline__ void mma16816(float* c, const uint32_t* a, const uint32_t* b) {
    asm volatile("mma.sync.aligned.m16n8k16.row.col.f32.bf16.bf16.f32 "
                 "{%0,%1,%2,%3}, {%4,%5,%6,%7}, {%8,%9}, {%0,%1,%2,%3};\n"
                 : "+f"(c[0]), "+f"(c[1]), "+f"(c[2]), "+f"(c[3])
                 : "r"(a[0]), "r"(a[1]), "r"(a[2]), "r"(a[3]), "r"(b[0]), "r"(b[1]));
}
__device__ __forceinline__ void mma16816h(float* c, const uint32_t* a, const uint32_t* b) {
    asm volatile("mma.sync.aligned.m16n8k16.row.col.f32.f16.f16.f32 "
                 "{%0,%1,%2,%3}, {%4,%5,%6,%7}, {%8,%9}, {%0,%1,%2,%3};\n"
                 : "+f"(c[0]), "+f"(c[1]), "+f"(c[2]), "+f"(c[3])
                 : "r"(a[0]), "r"(a[1]), "r"(a[2]), "r"(a[3]), "r"(b[0]), "r"(b[1]));
}
// t-major global row G -> bt-major source row
__device__ __forceinline__ int src_row(int G, int tmaj) {
    return tmaj ? ((G & 255) * 64 + (G >> 8)) : G;
}

// ---------------- prep kernels ----------------
__global__ void conv_f16(const float* __restrict__ x, __half* __restrict__ dst, size_t n)
{
    size_t i = ((size_t)blockIdx.x * blockDim.x + threadIdx.x) * 4;
    if (i >= n) return;
    float4 v = *reinterpret_cast<const float4*>(x + i);
    *reinterpret_cast<__half2*>(dst + i)     = __floats2half2_rn(v.x, v.y);
    *reinterpret_cast<__half2*>(dst + i + 2) = __floats2half2_rn(v.z, v.w);
}

__global__ void conv2_f16(const float* __restrict__ s1, int n1,
                          const float* __restrict__ s2, int n2,
                          __half* __restrict__ dst)
{
    int i = (blockIdx.x * blockDim.x + threadIdx.x) * 4;
    if (i >= n1 + n2) return;
    const float* src = (i < n1) ? s1 + i : s2 + (i - n1);
    float4 v = *reinterpret_cast<const float4*>(src);
    *reinterpret_cast<__half2*>(dst + i)     = __floats2half2_rn(v.x, v.y);
    *reinterpret_cast<__half2*>(dst + i + 2) = __floats2half2_rn(v.z, v.w);
}

__global__ void split2_bf16(const float* __restrict__ s1, int n1,
                            const float* __restrict__ s2, int n2,
                            __nv_bfloat16* __restrict__ hi,
                            __nv_bfloat16* __restrict__ lo)
{
    int i = (blockIdx.x * blockDim.x + threadIdx.x) * 4;
    if (i >= n1 + n2) return;
    const float* src = (i < n1) ? s1 + i : s2 + (i - n1);
    float4 v = *reinterpret_cast<const float4*>(src);
    __nv_bfloat16 h0 = __float2bfloat16(v.x), h1 = __float2bfloat16(v.y);
    __nv_bfloat16 h2 = __float2bfloat16(v.z), h3 = __float2bfloat16(v.w);
    __nv_bfloat162 a, b, c, d;
    a.x = h0; a.y = h1; b.x = h2; b.y = h3;
    c.x = __float2bfloat16(v.x - __bfloat162float(h0));
    c.y = __float2bfloat16(v.y - __bfloat162float(h1));
    d.x = __float2bfloat16(v.z - __bfloat162float(h2));
    d.y = __float2bfloat16(v.w - __bfloat162float(h3));
    *reinterpret_cast<__nv_bfloat162*>(hi + i)     = a;
    *reinterpret_cast<__nv_bfloat162*>(hi + i + 2) = b;
    *reinterpret_cast<__nv_bfloat162*>(lo + i)     = c;
    *reinterpret_cast<__nv_bfloat162*>(lo + i + 2) = d;
}

__global__ void concat2(float* __restrict__ dst,
                        const float* __restrict__ s1, int n1,
                        const float* __restrict__ s2, int n2)
{
    int i = blockIdx.x * blockDim.x + threadIdx.x;
    if (i < n1 + n2) dst[i] = (i < n1) ? s1[i] : s2[i - n1];
}

// ---------------- single-pass fp16 NT GEMM ----------------
// C[m,n] = bias[n] + sum_k A[m,k]*B[n,k]; fp16 in, fp32 accum, OutT out.
// WN: additionally store cols [1024,1536) as fp32 to Cn (i_n slice, stride H_).
template <typename OutT, bool WN>
__global__ void __launch_bounds__(256)
mma_f16(const __half* __restrict__ A, int lda,
        const __half* __restrict__ B, int ldb,
        const float* __restrict__ bias,
        OutT* __restrict__ C, int ldc, int K, int row_off, int tmaj,
        float* __restrict__ Cn)
{
    extern __shared__ __half smemh[];
    constexpr int LDK   = 40;
    constexpr int MAT   = 128 * LDK;
    constexpr int STAGE = 2 * MAT;
    const int tid  = threadIdx.x;
    const int lane = tid & 31;
    const int warp = tid >> 5;
    const int wm   = warp >> 2;
    const int wn   = warp & 3;
    const int m0   = blockIdx.y * 128 + row_off;
    const int n0   = blockIdx.x * 128;
    const uint32_t sb = (uint32_t)__cvta_generic_to_shared(smemh);

    float c[4][4][4];
#pragma unroll
    for (int i = 0; i < 4; i++)
#pragma unroll
        for (int j = 0; j < 4; j++)
#pragma unroll
            for (int r = 0; r < 4; r++) c[i][j][r] = 0.f;

    const int kc = (tid & 3) * 8;
    auto load_stage = [&](int stage, int k0) {
#pragma unroll
        for (int cchunk = 0; cchunk < 4; cchunk++) {
            int mat = cchunk >> 1;
            int r   = ((cchunk & 1) * 256 + tid) >> 2;
            const __half* g = (mat == 0)
                ? A + (size_t)src_row(m0 + r, tmaj) * lda + k0 + kc
                : B + (size_t)(n0 + r) * ldb + k0 + kc;
            uint32_t s = sb + (uint32_t)(stage * STAGE + mat * MAT + r * LDK + kc) * 2u;
            cpasync16(s, g);
        }
    };

    const int NT = K >> 5;
    load_stage(0, 0);
    cp_commit();

    const int rowA = (lane & 7) + ((lane >> 3) & 1) * 8;
    const int colA = (lane >> 4) * 8;
    const int rowB = (lane & 7) + (lane >> 4) * 8;
    const int colB = ((lane >> 3) & 1) * 8;

    for (int t = 0; t < NT; ++t) {
        if (t + 1 < NT) {
            load_stage((t + 1) & 1, (t + 1) * 32);
            cp_commit();
            cp_wait<1>();
        } else {
            cp_wait<0>();
        }
        __syncthreads();

        const uint32_t st = sb + (uint32_t)((t & 1) * STAGE) * 2u;
#pragma unroll
        for (int kk = 0; kk < 32; kk += 16) {
            uint32_t ah[4][4], bh[2][4];
#pragma unroll
            for (int im = 0; im < 4; im++) {
                uint32_t off = (uint32_t)((wm * 64 + im * 16 + rowA) * LDK + kk + colA) * 2u;
                ldsm4(ah[im], st + off);
            }
#pragma unroll
            for (int p = 0; p < 2; p++) {
                uint32_t off = (uint32_t)((wn * 32 + p * 16 + rowB) * LDK + kk + colB) * 2u;
                ldsm4(bh[p], st + (uint32_t)(MAT * 2) + off);
            }
#pragma unroll
            for (int im = 0; im < 4; im++)
#pragma unroll
                for (int in_ = 0; in_ < 4; in_++)
                    mma16816h(c[im][in_], ah[im], &bh[in_ >> 1][(in_ & 1) * 2]);
        }
        __syncthreads();
    }

    const int g  = lane >> 2;
    const int tq = lane & 3;
#pragma unroll
    for (int im = 0; im < 4; im++)
#pragma unroll
        for (int in_ = 0; in_ < 4; in_++) {
            int row = m0 + wm * 64 + im * 16 + g;
            int col = n0 + wn * 32 + in_ * 8 + tq * 2;
            float2 bv = *reinterpret_cast<const float2*>(bias + col);
            float v0 = c[im][in_][0] + bv.x, v1 = c[im][in_][1] + bv.y;
            float v2 = c[im][in_][2] + bv.x, v3 = c[im][in_][3] + bv.y;
            if constexpr (sizeof(OutT) == 2) {
                *reinterpret_cast<__half2*>(C + (size_t)row * ldc + col)       = __floats2half2_rn(v0, v1);
                *reinterpret_cast<__half2*>(C + (size_t)(row + 8) * ldc + col) = __floats2half2_rn(v2, v3);
            } else {
                *reinterpret_cast<float2*>(C + (size_t)row * ldc + col)       = make_float2(v0, v1);
                *reinterpret_cast<float2*>(C + (size_t)(row + 8) * ldc + col) = make_float2(v2, v3);
            }
            if constexpr (WN) {
                if (col >= 1024) {
                    *reinterpret_cast<float2*>(Cn + (size_t)row * H_ + (col - 1024)) =
                        make_float2(v0, v1);
                    *reinterpret_cast<float2*>(Cn + (size_t)(row + 8) * H_ + (col - 1024)) =
                        make_float2(v2, v3);
                }
            }
        }
}

// ---------------- step GEMM (sequential phase): 64x64 tile, 4 warps, 3-pass bf16 ----------------
__global__ void __launch_bounds__(128)
mma_step(const __nv_bfloat16* __restrict__ Ahi, const __nv_bfloat16* __restrict__ Alo,
         const __nv_bfloat16* __restrict__ Bhi, const __nv_bfloat16* __restrict__ Blo,
         const float* __restrict__ bias,
         float* __restrict__ C)
{
    extern __shared__ __nv_bfloat16 smem_h[];
    constexpr int LDK   = 40;
    constexpr int MAT   = 64 * LDK;
    constexpr int STAGE = 4 * MAT;
    constexpr int LDA   = H_;
    constexpr int LDC   = 2048;
    const int tid  = threadIdx.x;
    const int lane = tid & 31;
    const int warp = tid >> 5;
    const int wm   = warp >> 1;
    const int wn   = warp & 1;
    const int m0   = blockIdx.y * 64;
    const int n0   = blockIdx.x * 64;
    const uint32_t sb = (uint32_t)__cvta_generic_to_shared(smem_h);

    float c[2][4][4];
#pragma unroll
    for (int i = 0; i < 2; i++)
#pragma unroll
        for (int j = 0; j < 4; j++)
#pragma unroll
            for (int r = 0; r < 4; r++) c[i][j][r] = 0.f;

    auto load_stage = [&](int stage, int k0) {
#pragma unroll
        for (int f = tid; f < 256; f += 128) {
            int r  = f >> 2;
            int kc = (f & 3) * 8;
            uint32_t s = sb + (uint32_t)(stage * STAGE + r * LDK + kc) * 2u;
            cpasync16(s,                           Ahi + (size_t)(m0 + r) * LDA + k0 + kc);
            cpasync16(s + (uint32_t)(MAT * 2),     Alo + (size_t)(m0 + r) * LDA + k0 + kc);
            cpasync16(s + (uint32_t)(2 * MAT * 2), Bhi + (size_t)(n0 + r) * LDA + k0 + kc);
            cpasync16(s + (uint32_t)(3 * MAT * 2), Blo + (size_t)(n0 + r) * LDA + k0 + kc);
        }
    };

    constexpr int NT = H_ / 32;
    load_stage(0, 0);
    cp_commit();

    const int rowA = (lane & 7) + ((lane >> 3) & 1) * 8;
    const int colA = (lane >> 4) * 8;
    const int rowB = (lane & 7) + (lane >> 4) * 8;
    const int colB = ((lane >> 3) & 1) * 8;

    for (int t = 0; t < NT; ++t) {
        if (t + 1 < NT) {
            load_stage((t + 1) & 1, (t + 1) * 32);
            cp_commit();
            cp_wait<1>();
        } else {
            cp_wait<0>();
        }
        __syncthreads();

        const uint32_t st = sb + (uint32_t)((t & 1) * STAGE) * 2u;
#pragma unroll
        for (int kk = 0; kk < 32; kk += 16) {
            uint32_t ah[2][4], al[2][4], bh[2][4], bl[2][4];
#pragma unroll
            for (int im = 0; im < 2; im++) {
                uint32_t off = (uint32_t)((wm * 32 + im * 16 + rowA) * LDK + kk + colA) * 2u;
                ldsm4(ah[im], st + off);
                ldsm4(al[im], st + (uint32_t)(MAT * 2) + off);
            }
#pragma unroll
            for (int p = 0; p < 2; p++) {
                uint32_t off = (uint32_t)((wn * 32 + p * 16 + rowB) * LDK + kk + colB) * 2u;
                ldsm4(bh[p], st + (uint32_t)(2 * MAT * 2) + off);
                ldsm4(bl[p], st + (uint32_t)(3 * MAT * 2) + off);
            }
#pragma unroll
            for (int im = 0; im < 2; im++)
#pragma unroll
                for (int in_ = 0; in_ < 4; in_++) {
                    float* cc = c[im][in_];
                    const uint32_t* bhp = &bh[in_ >> 1][(in_ & 1) * 2];
                    const uint32_t* blp = &bl[in_ >> 1][(in_ & 1) * 2];
                    mma16816(cc, ah[im], bhp);
                    mma16816(cc, ah[im], blp);
                    mma16816(cc, al[im], bhp);
                }
        }
        __syncthreads();
    }

    const int g  = lane >> 2;
    const int tq = lane & 3;
#pragma unroll
    for (int im = 0; im < 2; im++)
#pragma unroll
        for (int in_ = 0; in_ < 4; in_++) {
            int row = m0 + wm * 32 + im * 16 + g;
            int col = n0 + wn * 32 + in_ * 8 + tq * 2;
            float2 bv = *reinterpret_cast<const float2*>(bias + col);
            *reinterpret_cast<float2*>(C + (size_t)row * LDC + col) =
                make_float2(c[im][in_][0] + bv.x, c[im][in_][1] + bv.y);
            *reinterpret_cast<float2*>(C + (size_t)(row + 8) * LDC + col) =
                make_float2(c[im][in_][2] + bv.x, c[im][in_][3] + bv.y);
        }
}

// ---------------- per-step attention + GRU gate update (t-major kv/gin) ----------------
__global__ void __launch_bounds__(256)
attn_gate(int t,
          const float* __restrict__ stepC,
          const float* __restrict__ gin,      // i_n fp32, t-major rows
          const float* __restrict__ kvR,
          const float* __restrict__ kvI,
          float* __restrict__ hx,
          __nv_bfloat16* __restrict__ hxh,
          __nv_bfloat16* __restrict__ hxl,
          float* __restrict__ out)
{
    const int b   = blockIdx.x;
    const int tid = threadIdx.x;
    const int tm  = t * B_ + b;
    const int bt  = b * T_ + t;
    const int h   = tid * 2;
    const float* rowC = stepC + (size_t)b * 2048;
    const float* kR   = kvR + (size_t)tm * 2048;
    const float* kI   = kvI + (size_t)tm * 2048;

    float2 qv  = *reinterpret_cast<const float2*>(rowC + 1536 + h);
    float2 kr0 = *reinterpret_cast<const float2*>(kR + h);
    float2 kr1 = *reinterpret_cast<const float2*>(kR + 1024 + h);
    float2 ki0 = *reinterpret_cast<const float2*>(kI + h);
    float2 ki1 = *reinterpret_cast<const float2*>(kI + 1024 + h);

    float s0r = qv.x * kr0.x + qv.y * kr0.y;
    float s1r = qv.x * kr1.x + qv.y * kr1.y;
    float s0i = qv.x * ki0.x + qv.y * ki0.y;
    float s1i = qv.x * ki1.x + qv.y * ki1.y;

#pragma unroll
    for (int o = 16; o > 0; o >>= 1) {
        s0r += __shfl_down_sync(0xffffffffu, s0r, o);
        s1r += __shfl_down_sync(0xffffffffu, s1r, o);
        s0i += __shfl_down_sync(0xffffffffu, s0i, o);
        s1i += __shfl_down_sync(0xffffffffu, s1i, o);
    }
    __shared__ float red[4][8];
    __shared__ float p[4];
    int warp = tid >> 5, lane = tid & 31;
    if (lane == 0) { red[0][warp] = s0r; red[1][warp] = s1r; red[2][warp] = s0i; red[3][warp] = s1i; }
    __syncthreads();
    if (tid == 0) {
        float t0 = 0.f, t1 = 0.f, t2 = 0.f, t3 = 0.f;
#pragma unroll
        for (int w = 0; w < 8; w++) { t0 += red[0][w]; t1 += red[1][w]; t2 += red[2][w]; t3 += red[3][w]; }
        const float scale = 0.044194173824159216f;  // 1/sqrt(512)
        t0 *= scale; t1 *= scale; t2 *= scale; t3 *= scale;
        float mr = fmaxf(t0, t1);
        float e0 = expf(t0 - mr), e1 = expf(t1 - mr);
        float inv = 1.f / (e0 + e1);
        p[0] = e0 * inv; p[1] = e1 * inv;
        float mi = fmaxf(t2, t3);
        float f0 = expf(t2 - mi), f1 = expf(t3 - mi);
        float inv2 = 1.f / (f0 + f1);
        p[2] = f0 * inv2; p[3] = f1 * inv2;
    }
    __syncthreads();
    float p0r = p[0], p1r = p[1], p0i = p[2], p1i = p[3];

    float2 vr0 = *reinterpret_cast<const float2*>(kR + 512 + h);
    float2 vr1 = *reinterpret_cast<const float2*>(kR + 1536 + h);
    float2 vi0 = *reinterpret_cast<const float2*>(kI + 512 + h);
    float2 vi1 = *reinterpret_cast<const float2*>(kI + 1536 + h);
    float2 h_r = *reinterpret_cast<const float2*>(rowC + h);
    float2 h_i = *reinterpret_cast<const float2*>(rowC + 512 + h);
    float2 h_n = *reinterpret_cast<const float2*>(rowC + 1024 + h);
    float2 i_n = *reinterpret_cast<const float2*>(gin + (size_t)tm * H_ + h);
    float2 hv  = *reinterpret_cast<const float2*>(hx + (size_t)b * H_ + h);

    float rg0 = 1.f / (1.f + expf(-(p0r * vr0.x + p1r * vr1.x + h_r.x)));
    float rg1 = 1.f / (1.f + expf(-(p0r * vr0.y + p1r * vr1.y + h_r.y)));
    float ig0 = 1.f / (1.f + expf(-(p0i * vi0.x + p1i * vi1.x + h_i.x)));
    float ig1 = 1.f / (1.f + expf(-(p0i * vi0.y + p1i * vi1.y + h_i.y)));
    float ng0 = tanhf(fmaf(rg0, h_n.x, i_n.x));
    float ng1 = tanhf(fmaf(rg1, h_n.y, i_n.y));
    float hy0 = ng0 + ig0 * (hv.x - ng0);
    float hy1 = ng1 + ig1 * (hv.y - ng1);

    *reinterpret_cast<float2*>(out + (size_t)bt * H_ + h) = make_float2(hy0, hy1);
    *reinterpret_cast<float2*>(hx + (size_t)b * H_ + h)   = make_float2(hy0, hy1);

    __nv_bfloat162 hh, ll;
    hh.x = __float2bfloat16(hy0);
    hh.y = __float2bfloat16(hy1);
    ll.x = __float2bfloat16(hy0 - __bfloat162float(hh.x));
    ll.y = __float2bfloat16(hy1 - __bfloat162float(hh.y));
    *reinterpret_cast<__nv_bfloat162*>(hxh + (size_t)b * H_ + h) = hh;
    *reinterpret_cast<__nv_bfloat162*>(hxl + (size_t)b * H_ + h) = ll;
}

// ---------------- launcher ----------------
extern "C" void kernel_launch(void* const* d_in, const int* in_sizes, int n_in,
                              void* d_out, int out_size)
{
    const float* input = (const float*)d_in[0];
    const float* aux0  = (const float*)d_in[1];
    const float* W_ih  = (const float*)d_in[2];
    const float* b_ih  = (const float*)d_in[3];
    const float* W_fh0 = (const float*)d_in[4];
    const float* b_fh0 = (const float*)d_in[5];
    const float* W_hh  = (const float*)d_in[6];
    const float* b_hh  = (const float*)d_in[7];
    const float* Wq    = (const float*)d_in[8];
    const float* bq    = (const float*)d_in[9];
    const float* Wk    = (const float*)d_in[10];
    const float* bk    = (const float*)d_in[11];
    const float* Wv    = (const float*)d_in[12];
    const float* bv    = (const float*)d_in[13];
    float* out = (float*)d_out;

    __nv_bfloat16 *wstep_hi, *wstep_lo, *hx_hi, *hx_lo;
    __half *in_f16, *aux_f16, *wih_f16, *wfh_f16, *wkv_f16, *gi_f16, *gf_f16;
    float *bkv, *gin32, *kvR, *kvI, *bstep, *hx, *stepC;
    cudaGetSymbolAddress((void**)&in_f16,   g_in_f16);
    cudaGetSymbolAddress((void**)&aux_f16,  g_aux_f16);
    cudaGetSymbolAddress((void**)&wih_f16,  g_wih_f16);
    cudaGetSymbolAddress((void**)&wfh_f16,  g_wfh_f16);
    cudaGetSymbolAddress((void**)&wkv_f16,  g_wkv_f16);
    cudaGetSymbolAddress((void**)&gi_f16,   g_gi_f16);
    cudaGetSymbolAddress((void**)&gf_f16,   g_gf_f16);
    cudaGetSymbolAddress((void**)&gin32,    g_in32);
    cudaGetSymbolAddress((void**)&bkv,      g_bkv);
    cudaGetSymbolAddress((void**)&kvR,      g_kvR);
    cudaGetSymbolAddress((void**)&kvI,      g_kvI);
    cudaGetSymbolAddress((void**)&wstep_hi, g_wstep_hi);
    cudaGetSymbolAddress((void**)&wstep_lo, g_wstep_lo);
    cudaGetSymbolAddress((void**)&bstep,    g_bstep);
    cudaGetSymbolAddress((void**)&hx,       g_hx);
    cudaGetSymbolAddress((void**)&hx_hi,    g_hx_hi);
    cudaGetSymbolAddress((void**)&hx_lo,    g_hx_lo);
    cudaGetSymbolAddress((void**)&stepC,    g_stepC);

    constexpr int SMEM_F16  = 40960;
    constexpr int SMEM_STEP = 4 * 64 * 40 * 2 * 2;

    // high-priority fork stream + events (leaked deliberately; destruction during
    // capture is illegal and kernel_launch runs only twice)
    int prlo = 0, prhi = 0;
    cudaDeviceGetStreamPriorityRange(&prlo, &prhi);
    cudaStream_t s2;
    cudaStreamCreateWithPriority(&s2, cudaStreamNonBlocking, prhi);
    cudaEvent_t evc[NCHUNK], evdone;
    for (int c = 0; c < NCHUNK; c++) cudaEventCreateWithFlags(&evc[c], cudaEventDisableTiming);
    cudaEventCreateWithFlags(&evdone, cudaEventDisableTiming);

    auto nblk = [](size_t n) { return (unsigned)((n / 4 + 255) / 256); };

    // ---- prep (origin stream) ----
    conv_f16<<<nblk((size_t)BT_ * DIN_), 256>>>(input, in_f16, (size_t)BT_ * DIN_);
    conv_f16<<<nblk((size_t)BT_ * DIN_), 256>>>(aux0, aux_f16, (size_t)BT_ * DIN_);
    conv_f16<<<nblk((size_t)H3_ * DIN_), 256>>>(W_ih, wih_f16, (size_t)H3_ * DIN_);
    conv_f16<<<nblk((size_t)H2_ * DIN_), 256>>>(W_fh0, wfh_f16, (size_t)H2_ * DIN_);
    conv2_f16<<<(H2_ * H_ / 4 + 255) / 256, 256>>>(Wk, H_ * H_, Wv, H_ * H_, wkv_f16);
    split2_bf16<<<(2048 * H_ / 4 + 255) / 256, 256>>>(W_hh, H3_ * H_, Wq, H_ * H_, wstep_hi, wstep_lo);
    concat2<<<(H2_ + 255) / 256, 256>>>(bkv, bk, H_, bv, H_);
    concat2<<<(2048 + 255) / 256, 256>>>(bstep, b_hh, H3_, bq, H_);
    cudaMemsetAsync(hx, 0, (size_t)B_ * H_ * sizeof(float));
    cudaMemsetAsync(hx_hi, 0, (size_t)B_ * H_ * sizeof(__nv_bfloat16));
    cudaMemsetAsync(hx_lo, 0, (size_t)B_ * H_ * sizeof(__nv_bfloat16));

    // ---- parallel phase: chunked over t-major rows (origin stream) ----
    for (int c = 0; c < NCHUNK; c++) {
        const int ro = c * MCHUNK;
        // [i_r|i_i|i_n] = input @ W_ih^T + b_ih : fp16 out + fp32 i_n side-store
        mma_f16<__half, true><<<dim3(H3_ / 128, MCHUNK / 128), 256, SMEM_F16>>>(
            in_f16, DIN_, wih_f16, DIN_, b_ih, gi_f16, H3_, DIN_, ro, 1, gin32);
        // [t1|t2] = aux0 @ W_fh0^T + b_fh0
        mma_f16<__half, false><<<dim3(H2_ / 128, MCHUNK / 128), 256, SMEM_F16>>>(
            aux_f16, DIN_, wfh_f16, DIN_, b_fh0, gf_f16, H2_, DIN_, ro, 1, nullptr);
        // KV projections (t-major A rows)
        mma_f16<float, false><<<dim3(H2_ / 128, MCHUNK / 128), 256, SMEM_F16>>>(
            gf_f16, H2_, wkv_f16, H_, bkv, kvR, 2048, H_, ro, 0, nullptr);
        mma_f16<float, false><<<dim3(H2_ / 128, MCHUNK / 128), 256, SMEM_F16>>>(
            gi_f16, H3_, wkv_f16, H_, bkv, kvR + 1024, 2048, H_, ro, 0, nullptr);
        mma_f16<float, false><<<dim3(H2_ / 128, MCHUNK / 128), 256, SMEM_F16>>>(
            gf_f16 + 512, H2_, wkv_f16, H_, bkv, kvI, 2048, H_, ro, 0, nullptr);
        mma_f16<float, false><<<dim3(H2_ / 128, MCHUNK / 128), 256, SMEM_F16>>>(
            gi_f16 + 512, H3_, wkv_f16, H_, bkv, kvI + 1024, 2048, H_, ro, 0, nullptr);
        cudaEventRecord(evc[c], 0);
    }

    // ---- sequential phase on high-priority forked stream, gated per chunk ----
    for (int c = 0; c < NCHUNK; c++) {
        cudaStreamWaitEvent(s2, evc[c], 0);
        for (int t = c * TCHUNK; t < (c + 1) * TCHUNK; ++t) {
            mma_step<<<dim3(2048 / 64, B_ / 64), 128, SMEM_STEP, s2>>>(
                hx_hi, hx_lo, wstep_hi, wstep_lo, bstep, stepC);
            attn_gate<<<B_, 256, 0, s2>>>(t, stepC, gin32, kvR, kvI, hx, hx_hi, hx_lo, out);
        }
    }
    cudaEventRecord(evdone, s2);
    cudaStreamWaitEvent(0, evdone, 0);

    // h_last (origin stream, after join)
    if (out_size >= (int)((size_t)BT_ * H_ + (size_t)B_ * H_)) {
        cudaMemcpyAsync(out + (size_t)BT_ * H_, hx,
                        (size_t)B_ * H_ * sizeof(float), cudaMemcpyDeviceToDevice);
    }
}

// round 17
// speedup vs baseline: 1.0392x; 1.0079x over previous
#include <cuda_runtime.h>
#include <cuda_bf16.h>
#include <cuda_fp16.h>
#include <math.h>
#include <stdint.h>

#define B_   256
#define T_   64
#define BT_  16384
#define DIN_ 2048
#define H_   512
#define H3_  1536
#define H2_  1024
#define NCHUNK 8
#define TCHUNK (T_ / NCHUNK)            // 8 timesteps per chunk
#define MCHUNK (B_ * TCHUNK)            // 2048 t-major rows per chunk

// ---------------- scratch (static device globals; no allocation) ----------------
__device__ __half        g_in_f16[(size_t)BT_ * DIN_];
__device__ __half        g_aux_f16[(size_t)BT_ * DIN_];
__device__ __half        g_wih_f16[(size_t)H3_ * DIN_];
__device__ __half        g_wfh_f16[(size_t)H2_ * DIN_];
__device__ __half        g_wkv_f16[H2_ * H_];
__device__ float         g_bkv[H2_];
__device__ __half        g_gi_f16[(size_t)BT_ * H3_];     // [i_r|i_i|i_n] fp16, t-major rows
__device__ __half        g_gf_f16[(size_t)BT_ * H2_];     // [t1|t2] fp16, t-major rows
__device__ float         g_in32[(size_t)BT_ * H_];        // i_n fp32, t-major rows
__device__ float         g_kvR[(size_t)BT_ * 2048];       // t-major rows [k0|v0|k1|v1]
__device__ float         g_kvI[(size_t)BT_ * 2048];
__device__ __nv_bfloat16 g_wstep_hi[2048 * H_], g_wstep_lo[2048 * H_];  // [W_hh; Wq]
__device__ float         g_bstep[2048];
__device__ float         g_hx[B_ * H_];
__device__ __nv_bfloat16 g_hx_hi[B_ * H_], g_hx_lo[B_ * H_];
__device__ float         g_stepC[B_ * 2048];

// ---------------- small helpers ----------------
__device__ __forceinline__ void cpasync16(uint32_t s, const void* g) {
    asm volatile("cp.async.cg.shared.global [%0], [%1], 16;\n" :: "r"(s), "l"(g));
}
__device__ __forceinline__ void cp_commit() {
    asm volatile("cp.async.commit_group;\n");
}
template <int N>
__device__ __forceinline__ void cp_wait() {
    asm volatile("cp.async.wait_group %0;\n" :: "n"(N));
}
__device__ __forceinline__ void ldsm4(uint32_t* r, uint32_t addr) {
    asm volatile("ldmatrix.sync.aligned.m8n8.x4.shared.b16 {%0,%1,%2,%3}, [%4];\n"
                 : "=r"(r[0]), "=r"(r[1]), "=r"(r[2]), "=r"(r[3]) : "r"(addr));
}
__device__ __forceinline__ void mma16816(float* c, const uint32_t* a, const uint32_t* b) {
    asm volatile("mma.sync.aligned.m16n8k16.row.col.f32.bf16.bf16.f32 "
                 "{%0,%1,%2,%3}, {%4,%5,%6,%7}, {%8,%9}, {%0,%1,%2,%3};\n"
                 : "+f"(c[0]), "+f"(c[1]), "+f"(c[2]), "+f"(c[3])
                 : "r"(a[0]), "r"(a[1]), "r"(a[2]), "r"(a[3]), "r"(b[0]), "r"(b[1]));
}
__device__ __forceinline__ void mma16816h(float* c, const uint32_t* a, const uint32_t* b) {
    asm volatile("mma.sync.aligned.m16n8k16.row.col.f32.f16.f16.f32 "
                 "{%0,%1,%2,%3}, {%4,%5,%6,%7}, {%8,%9}, {%0,%1,%2,%3};\n"
                 : "+f"(c[0]), "+f"(c[1]), "+f"(c[2]), "+f"(c[3])
                 : "r"(a[0]), "r"(a[1]), "r"(a[2]), "r"(a[3]), "r"(b[0]), "r"(b[1]));
}
// t-major global row G -> bt-major source row
__device__ __forceinline__ int src_row(int G, int tmaj) {
    return tmaj ? ((G & 255) * 64 + (G >> 8)) : G;
}

// ---------------- prep kernels ----------------
__global__ void conv_f16(const float* __restrict__ x, __half* __restrict__ dst, size_t n)
{
    size_t i = ((size_t)blockIdx.x * blockDim.x + threadIdx.x) * 4;
    if (i >= n) return;
    float4 v = *reinterpret_cast<const float4*>(x + i);
    *reinterpret_cast<__half2*>(dst + i)     = __floats2half2_rn(v.x, v.y);
    *reinterpret_cast<__half2*>(dst + i + 2) = __floats2half2_rn(v.z, v.w);
}

__global__ void conv2_f16(const float* __restrict__ s1, int n1,
                          const float* __restrict__ s2, int n2,
                          __half* __restrict__ dst)
{
    int i = (blockIdx.x * blockDim.x + threadIdx.x) * 4;
    if (i >= n1 + n2) return;
    const float* src = (i < n1) ? s1 + i : s2 + (i - n1);
    float4 v = *reinterpret_cast<const float4*>(src);
    *reinterpret_cast<__half2*>(dst + i)     = __floats2half2_rn(v.x, v.y);
    *reinterpret_cast<__half2*>(dst + i + 2) = __floats2half2_rn(v.z, v.w);
}

__global__ void split2_bf16(const float* __restrict__ s1, int n1,
                            const float* __restrict__ s2, int n2,
                            __nv_bfloat16* __restrict__ hi,
                            __nv_bfloat16* __restrict__ lo)
{
    int i = (blockIdx.x * blockDim.x + threadIdx.x) * 4;
    if (i >= n1 + n2) return;
    const float* src = (i < n1) ? s1 + i : s2 + (i - n1);
    float4 v = *reinterpret_cast<const float4*>(src);
    __nv_bfloat16 h0 = __float2bfloat16(v.x), h1 = __float2bfloat16(v.y);
    __nv_bfloat16 h2 = __float2bfloat16(v.z), h3 = __float2bfloat16(v.w);
    __nv_bfloat162 a, b, c, d;
    a.x = h0; a.y = h1; b.x = h2; b.y = h3;
    c.x = __float2bfloat16(v.x - __bfloat162float(h0));
    c.y = __float2bfloat16(v.y - __bfloat162float(h1));
    d.x = __float2bfloat16(v.z - __bfloat162float(h2));
    d.y = __float2bfloat16(v.w - __bfloat162float(h3));
    *reinterpret_cast<__nv_bfloat162*>(hi + i)     = a;
    *reinterpret_cast<__nv_bfloat162*>(hi + i + 2) = b;
    *reinterpret_cast<__nv_bfloat162*>(lo + i)     = c;
    *reinterpret_cast<__nv_bfloat162*>(lo + i + 2) = d;
}

__global__ void concat2(float* __restrict__ dst,
                        const float* __restrict__ s1, int n1,
                        const float* __restrict__ s2, int n2)
{
    int i = blockIdx.x * blockDim.x + threadIdx.x;
    if (i < n1 + n2) dst[i] = (i < n1) ? s1[i] : s2[i - n1];
}

// ---------------- single-pass fp16 NT GEMM ----------------
// C[m,n] = bias[n] + sum_k A[m,k]*B[n,k]; fp16 in, fp32 accum, OutT out.
// WN: additionally store cols [1024,1536) as fp32 to Cn (i_n slice, stride H_).
template <typename OutT, bool WN>
__global__ void __launch_bounds__(256)
mma_f16(const __half* __restrict__ A, int lda,
        const __half* __restrict__ B, int ldb,
        const float* __restrict__ bias,
        OutT* __restrict__ C, int ldc, int K, int row_off, int tmaj,
        float* __restrict__ Cn)
{
    extern __shared__ __half smemh[];
    constexpr int LDK   = 40;
    constexpr int MAT   = 128 * LDK;
    constexpr int STAGE = 2 * MAT;
    const int tid  = threadIdx.x;
    const int lane = tid & 31;
    const int warp = tid >> 5;
    const int wm   = warp >> 2;
    const int wn   = warp & 3;
    const int m0   = blockIdx.y * 128 + row_off;
    const int n0   = blockIdx.x * 128;
    const uint32_t sb = (uint32_t)__cvta_generic_to_shared(smemh);

    float c[4][4][4];
#pragma unroll
    for (int i = 0; i < 4; i++)
#pragma unroll
        for (int j = 0; j < 4; j++)
#pragma unroll
            for (int r = 0; r < 4; r++) c[i][j][r] = 0.f;

    const int kc = (tid & 3) * 8;
    auto load_stage = [&](int stage, int k0) {
#pragma unroll
        for (int cchunk = 0; cchunk < 4; cchunk++) {
            int mat = cchunk >> 1;
            int r   = ((cchunk & 1) * 256 + tid) >> 2;
            const __half* g = (mat == 0)
                ? A + (size_t)src_row(m0 + r, tmaj) * lda + k0 + kc
                : B + (size_t)(n0 + r) * ldb + k0 + kc;
            uint32_t s = sb + (uint32_t)(stage * STAGE + mat * MAT + r * LDK + kc) * 2u;
            cpasync16(s, g);
        }
    };

    const int NT = K >> 5;
    load_stage(0, 0);
    cp_commit();

    const int rowA = (lane & 7) + ((lane >> 3) & 1) * 8;
    const int colA = (lane >> 4) * 8;
    const int rowB = (lane & 7) + (lane >> 4) * 8;
    const int colB = ((lane >> 3) & 1) * 8;

    for (int t = 0; t < NT; ++t) {
        if (t + 1 < NT) {
            load_stage((t + 1) & 1, (t + 1) * 32);
            cp_commit();
            cp_wait<1>();
        } else {
            cp_wait<0>();
        }
        __syncthreads();

        const uint32_t st = sb + (uint32_t)((t & 1) * STAGE) * 2u;
#pragma unroll
        for (int kk = 0; kk < 32; kk += 16) {
            uint32_t ah[4][4], bh[2][4];
#pragma unroll
            for (int im = 0; im < 4; im++) {
                uint32_t off = (uint32_t)((wm * 64 + im * 16 + rowA) * LDK + kk + colA) * 2u;
                ldsm4(ah[im], st + off);
            }
#pragma unroll
            for (int p = 0; p < 2; p++) {
                uint32_t off = (uint32_t)((wn * 32 + p * 16 + rowB) * LDK + kk + colB) * 2u;
                ldsm4(bh[p], st + (uint32_t)(MAT * 2) + off);
            }
#pragma unroll
            for (int im = 0; im < 4; im++)
#pragma unroll
                for (int in_ = 0; in_ < 4; in_++)
                    mma16816h(c[im][in_], ah[im], &bh[in_ >> 1][(in_ & 1) * 2]);
        }
        __syncthreads();
    }

    const int g  = lane >> 2;
    const int tq = lane & 3;
#pragma unroll
    for (int im = 0; im < 4; im++)
#pragma unroll
        for (int in_ = 0; in_ < 4; in_++) {
            int row = m0 + wm * 64 + im * 16 + g;
            int col = n0 + wn * 32 + in_ * 8 + tq * 2;
            float2 bv = *reinterpret_cast<const float2*>(bias + col);
            float v0 = c[im][in_][0] + bv.x, v1 = c[im][in_][1] + bv.y;
            float v2 = c[im][in_][2] + bv.x, v3 = c[im][in_][3] + bv.y;
            if constexpr (sizeof(OutT) == 2) {
                *reinterpret_cast<__half2*>(C + (size_t)row * ldc + col)       = __floats2half2_rn(v0, v1);
                *reinterpret_cast<__half2*>(C + (size_t)(row + 8) * ldc + col) = __floats2half2_rn(v2, v3);
            } else {
                *reinterpret_cast<float2*>(C + (size_t)row * ldc + col)       = make_float2(v0, v1);
                *reinterpret_cast<float2*>(C + (size_t)(row + 8) * ldc + col) = make_float2(v2, v3);
            }
            if constexpr (WN) {
                if (col >= 1024) {
                    *reinterpret_cast<float2*>(Cn + (size_t)row * H_ + (col - 1024)) =
                        make_float2(v0, v1);
                    *reinterpret_cast<float2*>(Cn + (size_t)(row + 8) * H_ + (col - 1024)) =
                        make_float2(v2, v3);
                }
            }
        }
}

// ---------------- step GEMM (sequential phase): 64x64 tile, 4 warps, 3-pass bf16 ----------------
__global__ void __launch_bounds__(128)
mma_step(const __nv_bfloat16* __restrict__ Ahi, const __nv_bfloat16* __restrict__ Alo,
         const __nv_bfloat16* __restrict__ Bhi, const __nv_bfloat16* __restrict__ Blo,
         const float* __restrict__ bias,
         float* __restrict__ C)
{
    extern __shared__ __nv_bfloat16 smem_h[];
    constexpr int LDK   = 40;
    constexpr int MAT   = 64 * LDK;
    constexpr int STAGE = 4 * MAT;
    constexpr int LDA   = H_;
    constexpr int LDC   = 2048;
    const int tid  = threadIdx.x;
    const int lane = tid & 31;
    const int warp = tid >> 5;
    const int wm   = warp >> 1;
    const int wn   = warp & 1;
    const int m0   = blockIdx.y * 64;
    const int n0   = blockIdx.x * 64;
    const uint32_t sb = (uint32_t)__cvta_generic_to_shared(smem_h);

    float c[2][4][4];
#pragma unroll
    for (int i = 0; i < 2; i++)
#pragma unroll
        for (int j = 0; j < 4; j++)
#pragma unroll
            for (int r = 0; r < 4; r++) c[i][j][r] = 0.f;

    auto load_stage = [&](int stage, int k0) {
#pragma unroll
        for (int f = tid; f < 256; f += 128) {
            int r  = f >> 2;
            int kc = (f & 3) * 8;
            uint32_t s = sb + (uint32_t)(stage * STAGE + r * LDK + kc) * 2u;
            cpasync16(s,                           Ahi + (size_t)(m0 + r) * LDA + k0 + kc);
            cpasync16(s + (uint32_t)(MAT * 2),     Alo + (size_t)(m0 + r) * LDA + k0 + kc);
            cpasync16(s + (uint32_t)(2 * MAT * 2), Bhi + (size_t)(n0 + r) * LDA + k0 + kc);
            cpasync16(s + (uint32_t)(3 * MAT * 2), Blo + (size_t)(n0 + r) * LDA + k0 + kc);
        }
    };

    constexpr int NT = H_ / 32;
    load_stage(0, 0);
    cp_commit();

    const int rowA = (lane & 7) + ((lane >> 3) & 1) * 8;
    const int colA = (lane >> 4) * 8;
    const int rowB = (lane & 7) + (lane >> 4) * 8;
    const int colB = ((lane >> 3) & 1) * 8;

    for (int t = 0; t < NT; ++t) {
        if (t + 1 < NT) {
            load_stage((t + 1) & 1, (t + 1) * 32);
            cp_commit();
            cp_wait<1>();
        } else {
            cp_wait<0>();
        }
        __syncthreads();

        const uint32_t st = sb + (uint32_t)((t & 1) * STAGE) * 2u;
#pragma unroll
        for (int kk = 0; kk < 32; kk += 16) {
            uint32_t ah[2][4], al[2][4], bh[2][4], bl[2][4];
#pragma unroll
            for (int im = 0; im < 2; im++) {
                uint32_t off = (uint32_t)((wm * 32 + im * 16 + rowA) * LDK + kk + colA) * 2u;
                ldsm4(ah[im], st + off);
                ldsm4(al[im], st + (uint32_t)(MAT * 2) + off);
            }
#pragma unroll
            for (int p = 0; p < 2; p++) {
                uint32_t off = (uint32_t)((wn * 32 + p * 16 + rowB) * LDK + kk + colB) * 2u;
                ldsm4(bh[p], st + (uint32_t)(2 * MAT * 2) + off);
                ldsm4(bl[p], st + (uint32_t)(3 * MAT * 2) + off);
            }
#pragma unroll
            for (int im = 0; im < 2; im++)
#pragma unroll
                for (int in_ = 0; in_ < 4; in_++) {
                    float* cc = c[im][in_];
                    const uint32_t* bhp = &bh[in_ >> 1][(in_ & 1) * 2];
                    const uint32_t* blp = &bl[in_ >> 1][(in_ & 1) * 2];
                    mma16816(cc, ah[im], bhp);
                    mma16816(cc, ah[im], blp);
                    mma16816(cc, al[im], bhp);
                }
        }
        __syncthreads();
    }

    const int g  = lane >> 2;
    const int tq = lane & 3;
#pragma unroll
    for (int im = 0; im < 2; im++)
#pragma unroll
        for (int in_ = 0; in_ < 4; in_++) {
            int row = m0 + wm * 32 + im * 16 + g;
            int col = n0 + wn * 32 + in_ * 8 + tq * 2;
            float2 bv = *reinterpret_cast<const float2*>(bias + col);
            *reinterpret_cast<float2*>(C + (size_t)row * LDC + col) =
                make_float2(c[im][in_][0] + bv.x, c[im][in_][1] + bv.y);
            *reinterpret_cast<float2*>(C + (size_t)(row + 8) * LDC + col) =
                make_float2(c[im][in_][2] + bv.x, c[im][in_][3] + bv.y);
        }
}

// ---------------- per-step attention + GRU gate update (t-major kv/gin) ----------------
__global__ void __launch_bounds__(256)
attn_gate(int t,
          const float* __restrict__ stepC,
          const float* __restrict__ gin,      // i_n fp32, t-major rows
          const float* __restrict__ kvR,
          const float* __restrict__ kvI,
          float* __restrict__ hx,
          __nv_bfloat16* __restrict__ hxh,
          __nv_bfloat16* __restrict__ hxl,
          float* __restrict__ out)
{
    const int b   = blockIdx.x;
    const int tid = threadIdx.x;
    const int tm  = t * B_ + b;
    const int bt  = b * T_ + t;
    const int h   = tid * 2;
    const float* rowC = stepC + (size_t)b * 2048;
    const float* kR   = kvR + (size_t)tm * 2048;
    const float* kI   = kvI + (size_t)tm * 2048;

    float2 qv  = *reinterpret_cast<const float2*>(rowC + 1536 + h);
    float2 kr0 = *reinterpret_cast<const float2*>(kR + h);
    float2 kr1 = *reinterpret_cast<const float2*>(kR + 1024 + h);
    float2 ki0 = *reinterpret_cast<const float2*>(kI + h);
    float2 ki1 = *reinterpret_cast<const float2*>(kI + 1024 + h);

    float s0r = qv.x * kr0.x + qv.y * kr0.y;
    float s1r = qv.x * kr1.x + qv.y * kr1.y;
    float s0i = qv.x * ki0.x + qv.y * ki0.y;
    float s1i = qv.x * ki1.x + qv.y * ki1.y;

#pragma unroll
    for (int o = 16; o > 0; o >>= 1) {
        s0r += __shfl_down_sync(0xffffffffu, s0r, o);
        s1r += __shfl_down_sync(0xffffffffu, s1r, o);
        s0i += __shfl_down_sync(0xffffffffu, s0i, o);
        s1i += __shfl_down_sync(0xffffffffu, s1i, o);
    }
    __shared__ float red[4][8];
    __shared__ float p[4];
    int warp = tid >> 5, lane = tid & 31;
    if (lane == 0) { red[0][warp] = s0r; red[1][warp] = s1r; red[2][warp] = s0i; red[3][warp] = s1i; }
    __syncthreads();
    if (tid == 0) {
        float t0 = 0.f, t1 = 0.f, t2 = 0.f, t3 = 0.f;
#pragma unroll
        for (int w = 0; w < 8; w++) { t0 += red[0][w]; t1 += red[1][w]; t2 += red[2][w]; t3 += red[3][w]; }
        const float scale = 0.044194173824159216f;  // 1/sqrt(512)
        t0 *= scale; t1 *= scale; t2 *= scale; t3 *= scale;
        float mr = fmaxf(t0, t1);
        float e0 = expf(t0 - mr), e1 = expf(t1 - mr);
        float inv = 1.f / (e0 + e1);
        p[0] = e0 * inv; p[1] = e1 * inv;
        float mi = fmaxf(t2, t3);
        float f0 = expf(t2 - mi), f1 = expf(t3 - mi);
        float inv2 = 1.f / (f0 + f1);
        p[2] = f0 * inv2; p[3] = f1 * inv2;
    }
    __syncthreads();
    float p0r = p[0], p1r = p[1], p0i = p[2], p1i = p[3];

    float2 vr0 = *reinterpret_cast<const float2*>(kR + 512 + h);
    float2 vr1 = *reinterpret_cast<const float2*>(kR + 1536 + h);
    float2 vi0 = *reinterpret_cast<const float2*>(kI + 512 + h);
    float2 vi1 = *reinterpret_cast<const float2*>(kI + 1536 + h);
    float2 h_r = *reinterpret_cast<const float2*>(rowC + h);
    float2 h_i = *reinterpret_cast<const float2*>(rowC + 512 + h);
    float2 h_n = *reinterpret_cast<const float2*>(rowC + 1024 + h);
    float2 i_n = *reinterpret_cast<const float2*>(gin + (size_t)tm * H_ + h);
    float2 hv  = *reinterpret_cast<const float2*>(hx + (size_t)b * H_ + h);

    float rg0 = 1.f / (1.f + expf(-(p0r * vr0.x + p1r * vr1.x + h_r.x)));
    float rg1 = 1.f / (1.f + expf(-(p0r * vr0.y + p1r * vr1.y + h_r.y)));
    float ig0 = 1.f / (1.f + expf(-(p0i * vi0.x + p1i * vi1.x + h_i.x)));
    float ig1 = 1.f / (1.f + expf(-(p0i * vi0.y + p1i * vi1.y + h_i.y)));
    float ng0 = tanhf(fmaf(rg0, h_n.x, i_n.x));
    float ng1 = tanhf(fmaf(rg1, h_n.y, i_n.y));
    float hy0 = ng0 + ig0 * (hv.x - ng0);
    float hy1 = ng1 + ig1 * (hv.y - ng1);

    *reinterpret_cast<float2*>(out + (size_t)bt * H_ + h) = make_float2(hy0, hy1);
    *reinterpret_cast<float2*>(hx + (size_t)b * H_ + h)   = make_float2(hy0, hy1);

    __nv_bfloat162 hh, ll;
    hh.x = __float2bfloat16(hy0);
    hh.y = __float2bfloat16(hy1);
    ll.x = __float2bfloat16(hy0 - __bfloat162float(hh.x));
    ll.y = __float2bfloat16(hy1 - __bfloat162float(hh.y));
    *reinterpret_cast<__nv_bfloat162*>(hxh + (size_t)b * H_ + h) = hh;
    *reinterpret_cast<__nv_bfloat162*>(hxl + (size_t)b * H_ + h) = ll;
}

// ---------------- launcher ----------------
extern "C" void kernel_launch(void* const* d_in, const int* in_sizes, int n_in,
                              void* d_out, int out_size)
{
    const float* input = (const float*)d_in[0];
    const float* aux0  = (const float*)d_in[1];
    const float* W_ih  = (const float*)d_in[2];
    const float* b_ih  = (const float*)d_in[3];
    const float* W_fh0 = (const float*)d_in[4];
    const float* b_fh0 = (const float*)d_in[5];
    const float* W_hh  = (const float*)d_in[6];
    const float* b_hh  = (const float*)d_in[7];
    const float* Wq    = (const float*)d_in[8];
    const float* bq    = (const float*)d_in[9];
    const float* Wk    = (const float*)d_in[10];
    const float* bk    = (const float*)d_in[11];
    const float* Wv    = (const float*)d_in[12];
    const float* bv    = (const float*)d_in[13];
    float* out = (float*)d_out;

    __nv_bfloat16 *wstep_hi, *wstep_lo, *hx_hi, *hx_lo;
    __half *in_f16, *aux_f16, *wih_f16, *wfh_f16, *wkv_f16, *gi_f16, *gf_f16;
    float *bkv, *gin32, *kvR, *kvI, *bstep, *hx, *stepC;
    cudaGetSymbolAddress((void**)&in_f16,   g_in_f16);
    cudaGetSymbolAddress((void**)&aux_f16,  g_aux_f16);
    cudaGetSymbolAddress((void**)&wih_f16,  g_wih_f16);
    cudaGetSymbolAddress((void**)&wfh_f16,  g_wfh_f16);
    cudaGetSymbolAddress((void**)&wkv_f16,  g_wkv_f16);
    cudaGetSymbolAddress((void**)&gi_f16,   g_gi_f16);
    cudaGetSymbolAddress((void**)&gf_f16,   g_gf_f16);
    cudaGetSymbolAddress((void**)&gin32,    g_in32);
    cudaGetSymbolAddress((void**)&bkv,      g_bkv);
    cudaGetSymbolAddress((void**)&kvR,      g_kvR);
    cudaGetSymbolAddress((void**)&kvI,      g_kvI);
    cudaGetSymbolAddress((void**)&wstep_hi, g_wstep_hi);
    cudaGetSymbolAddress((void**)&wstep_lo, g_wstep_lo);
    cudaGetSymbolAddress((void**)&bstep,    g_bstep);
    cudaGetSymbolAddress((void**)&hx,       g_hx);
    cudaGetSymbolAddress((void**)&hx_hi,    g_hx_hi);
    cudaGetSymbolAddress((void**)&hx_lo,    g_hx_lo);
    cudaGetSymbolAddress((void**)&stepC,    g_stepC);

    constexpr int SMEM_F16  = 40960;
    constexpr int SMEM_STEP = 4 * 64 * 40 * 2 * 2;

    // high-priority fork stream + events (leaked deliberately; destruction during
    // capture is illegal and kernel_launch runs only twice)
    int prlo = 0, prhi = 0;
    cudaDeviceGetStreamPriorityRange(&prlo, &prhi);
    cudaStream_t s2;
    cudaStreamCreateWithPriority(&s2, cudaStreamNonBlocking, prhi);
    cudaEvent_t evc[NCHUNK], evdone;
    for (int c = 0; c < NCHUNK; c++) cudaEventCreateWithFlags(&evc[c], cudaEventDisableTiming);
    cudaEventCreateWithFlags(&evdone, cudaEventDisableTiming);

    auto nblk = [](size_t n) { return (unsigned)((n / 4 + 255) / 256); };

    // ---- prep (origin stream) ----
    conv_f16<<<nblk((size_t)BT_ * DIN_), 256>>>(input, in_f16, (size_t)BT_ * DIN_);
    conv_f16<<<nblk((size_t)BT_ * DIN_), 256>>>(aux0, aux_f16, (size_t)BT_ * DIN_);
    conv_f16<<<nblk((size_t)H3_ * DIN_), 256>>>(W_ih, wih_f16, (size_t)H3_ * DIN_);
    conv_f16<<<nblk((size_t)H2_ * DIN_), 256>>>(W_fh0, wfh_f16, (size_t)H2_ * DIN_);
    conv2_f16<<<(H2_ * H_ / 4 + 255) / 256, 256>>>(Wk, H_ * H_, Wv, H_ * H_, wkv_f16);
    split2_bf16<<<(2048 * H_ / 4 + 255) / 256, 256>>>(W_hh, H3_ * H_, Wq, H_ * H_, wstep_hi, wstep_lo);
    concat2<<<(H2_ + 255) / 256, 256>>>(bkv, bk, H_, bv, H_);
    concat2<<<(2048 + 255) / 256, 256>>>(bstep, b_hh, H3_, bq, H_);
    cudaMemsetAsync(hx, 0, (size_t)B_ * H_ * sizeof(float));
    cudaMemsetAsync(hx_hi, 0, (size_t)B_ * H_ * sizeof(__nv_bfloat16));
    cudaMemsetAsync(hx_lo, 0, (size_t)B_ * H_ * sizeof(__nv_bfloat16));

    // ---- parallel phase: chunked over t-major rows (origin stream) ----
    for (int c = 0; c < NCHUNK; c++) {
        const int ro = c * MCHUNK;
        // [i_r|i_i|i_n] = input @ W_ih^T + b_ih : fp16 out + fp32 i_n side-store
        mma_f16<__half, true><<<dim3(H3_ / 128, MCHUNK / 128), 256, SMEM_F16>>>(
            in_f16, DIN_, wih_f16, DIN_, b_ih, gi_f16, H3_, DIN_, ro, 1, gin32);
        // [t1|t2] = aux0 @ W_fh0^T + b_fh0
        mma_f16<__half, false><<<dim3(H2_ / 128, MCHUNK / 128), 256, SMEM_F16>>>(
            aux_f16, DIN_, wfh_f16, DIN_, b_fh0, gf_f16, H2_, DIN_, ro, 1, nullptr);
        // KV projections (t-major A rows)
        mma_f16<float, false><<<dim3(H2_ / 128, MCHUNK / 128), 256, SMEM_F16>>>(
            gf_f16, H2_, wkv_f16, H_, bkv, kvR, 2048, H_, ro, 0, nullptr);
        mma_f16<float, false><<<dim3(H2_ / 128, MCHUNK / 128), 256, SMEM_F16>>>(
            gi_f16, H3_, wkv_f16, H_, bkv, kvR + 1024, 2048, H_, ro, 0, nullptr);
        mma_f16<float, false><<<dim3(H2_ / 128, MCHUNK / 128), 256, SMEM_F16>>>(
            gf_f16 + 512, H2_, wkv_f16, H_, bkv, kvI, 2048, H_, ro, 0, nullptr);
        mma_f16<float, false><<<dim3(H2_ / 128, MCHUNK / 128), 256, SMEM_F16>>>(
            gi_f16 + 512, H3_, wkv_f16, H_, bkv, kvI + 1024, 2048, H_, ro, 0, nullptr);
        cudaEventRecord(evc[c], 0);
    }

    // ---- sequential phase on high-priority forked stream, gated per chunk ----
    for (int c = 0; c < NCHUNK; c++) {
        cudaStreamWaitEvent(s2, evc[c], 0);
        for (int t = c * TCHUNK; t < (c + 1) * TCHUNK; ++t) {
            mma_step<<<dim3(2048 / 64, B_ / 64), 128, SMEM_STEP, s2>>>(
                hx_hi, hx_lo, wstep_hi, wstep_lo, bstep, stepC);
            attn_gate<<<B_, 256, 0, s2>>>(t, stepC, gin32, kvR, kvI, hx, hx_hi, hx_lo, out);
        }
    }
    cudaEventRecord(evdone, s2);
    cudaStreamWaitEvent(0, evdone, 0);

    // h_last (origin stream, after join)
    if (out_size >= (int)((size_t)BT_ * H_ + (size_t)B_ * H_)) {
        cudaMemcpyAsync(out + (size_t)BT_ * H_, hx,
                        (size_t)B_ * H_ * sizeof(float), cudaMemcpyDeviceToDevice);
    }
}